// round 14
// baseline (speedup 1.0000x reference)
#include <cuda_runtime.h>
#include <stdint.h>

// Problem constants (fixed shapes per setup_inputs)
#define BATCH 4
#define NPTS  2048
#define NB    (BATCH * NPTS)        // 8192 (b,n) pairs
#define GRID_DIM 64                 // coords in [0,64)
#define PRIOR_VOX 4096              // 16^3
#define OCC_K 26
#define OCC_BASE ((size_t)NB * PRIOR_VOX)   // 33,554,432

// Padded byte occupancy map: index (x+1, y+1, z+1) in a 66^3 slab.
// Padding absorbs the +/-1 neighbor offsets -> no bounds checks on probes.
#define PADD 66
#define XSTRIDE (PADD * PADD)               // 4356
#define SLAB_BYTES (PADD * PADD * PADD)     // 287496
#define BSTRIDE 287504                      // slab rounded up to 16B multiple
#define SLAB_W4 (BSTRIDE / 16)              // 17969 uint4 words per slab

__device__ unsigned char g_occmap[BATCH * BSTRIDE];   // ~1.15 MB

// Linear offsets of the 26 neighbors in the padded map (dx*4356 + dy*66 + dz).
// First 6 entries are the face offsets (order matches reference).
__constant__ int c_loff[26] = {
    -XSTRIDE, XSTRIDE, -PADD, PADD, -1, 1,
    -XSTRIDE-PADD, -XSTRIDE+PADD, XSTRIDE-PADD, XSTRIDE+PADD,
    -XSTRIDE-1, -XSTRIDE+1, XSTRIDE-1, XSTRIDE+1,
    -PADD-1, -PADD+1, PADD-1, PADD+1,
    -XSTRIDE-PADD-1, -XSTRIDE-PADD+1, -XSTRIDE+PADD-1, -XSTRIDE+PADD+1,
    XSTRIDE-PADD-1, XSTRIDE-PADD+1, XSTRIDE+PADD-1, XSTRIDE+PADD+1};

// Build: one CTA per batch, 1024 threads. Zero the whole slab with uint4
// stores (this also keeps the entire map L2-warm for the hot kernel's probes
// every replay), sync, then stamp 2 points/thread with plain byte stores.
// No atomics anywhere.
__global__ __launch_bounds__(1024)
void build_map_kernel(const int* __restrict__ coords) {
    const int b = blockIdx.x;
    const int t = threadIdx.x;
    unsigned char* om = g_occmap + b * BSTRIDE;
    uint4* om4 = reinterpret_cast<uint4*>(om);
    const uint4 z4 = make_uint4(0u, 0u, 0u, 0u);

    #pragma unroll
    for (int i = 0; i < 18; i++) {
        int w = t + i * 1024;
        if (w < SLAB_W4) om4[w] = z4;
    }
    __syncthreads();

    const int* c = coords + b * NPTS * 3;
    #pragma unroll
    for (int i = 0; i < NPTS / 1024; i++) {
        int n = t + i * 1024;
        int x = c[n * 3 + 0];
        int y = c[n * 3 + 1];
        int z = c[n * 3 + 2];
        om[(x + 1) * XSTRIDE + (y + 1) * PADD + (z + 1)] = 1;
    }
}

// PROVEN hot-kernel shape: one CTA per (b,n), 256 threads. Warp 0 lanes
// 0..25 probe the padded byte map (1 byte load, no bounds check), write occ,
// ballot the face mask. Then all 256 threads stream the 4096-float prior
// tile as 4 fully contiguous warp-wide float4 stores each.
__global__ __launch_bounds__(256, 8)
void prior_occ_kernel(const int* __restrict__ coords, float* __restrict__ out) {
    const int bn = blockIdx.x;
    const int b  = bn >> 11;
    const int t  = threadIdx.x;

    __shared__ unsigned s_mask;

    if (t < 32) {
        const int x = coords[bn * 3 + 0];
        const int y = coords[bn * 3 + 1];
        const int z = coords[bn * 3 + 2];
        const int base = b * BSTRIDE + (x + 1) * XSTRIDE + (y + 1) * PADD + (z + 1);
        bool present = false;
        if (t < OCC_K) {
            present = (__ldcg(&g_occmap[base + c_loff[t]]) != 0);
            out[OCC_BASE + (size_t)bn * OCC_K + t] = present ? 1.0f : 0.0f;
        }
        unsigned bal = __ballot_sync(0xffffffffu, present);
        if (t == 0) s_mask = bal;
    }
    __syncthreads();

    const unsigned m = s_mask;
    const float r15 = 1.0f / 15.0f;
    float* out_p = out + (size_t)bn * PRIOR_VOX;

    // v = t*4 + q*1024; i = (t>>6) + 4q, j = (t>>2)&15, k0 = (t&3)*4.
    // y- and z-face mins are invariant across the 4 q iterations.
    const float gy = (float)((t >> 2) & 15) * r15;
    const int   k0 = (t & 3) << 2;
    const int   i0 = t >> 6;

    float ybase = 1.0f;
    if (!(m & 4u))  ybase = fminf(ybase, gy);
    if (!(m & 8u))  ybase = fminf(ybase, 1.0f - gy);

    float yz[4];
    #pragma unroll
    for (int kk = 0; kk < 4; kk++) {
        float gz = (float)(k0 + kk) * r15;
        float v = ybase;
        if (!(m & 16u)) v = fminf(v, gz);
        if (!(m & 32u)) v = fminf(v, 1.0f - gz);
        yz[kk] = v;
    }

    #pragma unroll
    for (int q = 0; q < 4; q++) {
        float gx = (float)(i0 + 4 * q) * r15;   // exact: matches linspace rounding
        float xv = 1.0f;
        if (!(m & 1u)) xv = fminf(xv, gx);
        if (!(m & 2u)) xv = fminf(xv, 1.0f - gx);
        float4 r;
        r.x = fminf(yz[0], xv);
        r.y = fminf(yz[1], xv);
        r.z = fminf(yz[2], xv);
        r.w = fminf(yz[3], xv);
        *reinterpret_cast<float4*>(out_p + (t << 2) + (q << 10)) = r;
    }
}

extern "C" void kernel_launch(void* const* d_in, const int* in_sizes, int n_in,
                              void* d_out, int out_size) {
    const int* coords = (const int*)d_in[0];
    float* out = (float*)d_out;

    build_map_kernel<<<BATCH, 1024>>>(coords);
    prior_occ_kernel<<<NB, 256>>>(coords, out);
}

// round 16
// speedup vs baseline: 1.0769x; 1.0769x over previous
#include <cuda_runtime.h>
#include <stdint.h>

// Problem constants (fixed shapes per setup_inputs)
#define BATCH 4
#define NPTS  2048
#define NB    (BATCH * NPTS)        // 8192 (b,n) pairs
#define GRID_DIM 64                 // coords in [0,64)
#define BITMAP_WORDS (GRID_DIM * GRID_DIM * GRID_DIM / 32)  // 8192 words = 32KB
#define PRIOR_VOX 4096              // 16^3
#define OCC_K 26
#define OCC_BASE ((size_t)NB * PRIOR_VOX)   // 33,554,432

// Per-(b,n) 26-bit neighbor mask (32 KB, static __device__ per harness rules).
__device__ unsigned int g_mask26[NB];

// 26 neighbor offsets; first 6 are the face offsets (order matches reference).
__constant__ int8_t c_noff[26][3] = {
    {-1,0,0},{1,0,0},{0,-1,0},{0,1,0},{0,0,-1},{0,0,1},
    {-1,-1,0},{-1,1,0},{1,-1,0},{1,1,0},
    {-1,0,-1},{-1,0,1},{1,0,-1},{1,0,1},
    {0,-1,-1},{0,-1,1},{0,1,-1},{0,1,1},
    {-1,-1,-1},{-1,-1,1},{-1,1,-1},{-1,1,1},
    {1,-1,-1},{1,-1,1},{1,1,-1},{1,1,1}};

// Kernel 1: one CTA per batch, 1024 threads. The batch's 64^3 occupancy
// bitmap lives entirely in SHARED memory (32 KB): zero it, atomicOr the 2048
// points, then probe all 26 neighbors per point via LDS (~100x the throughput
// of the R6 global-probe version) and emit only the coalesced mask array.
// No global scratch to keep warm, no global zeroing.
__global__ __launch_bounds__(1024)
void mask_kernel(const int* __restrict__ coords) {
    __shared__ unsigned int bm[BITMAP_WORDS];   // 32 KB
    const int b = blockIdx.x;
    const int t = threadIdx.x;

    #pragma unroll
    for (int i = 0; i < BITMAP_WORDS / 1024; i++)
        bm[t + i * 1024] = 0u;
    __syncthreads();

    const int* c = coords + b * NPTS * 3;
    int px[NPTS / 1024], py[NPTS / 1024], pz[NPTS / 1024];
    #pragma unroll
    for (int i = 0; i < NPTS / 1024; i++) {
        int n = t + i * 1024;
        px[i] = c[n * 3 + 0];
        py[i] = c[n * 3 + 1];
        pz[i] = c[n * 3 + 2];
        int idx = (px[i] << 12) | (py[i] << 6) | pz[i];   // x*4096+y*64+z
        atomicOr(&bm[idx >> 5], 1u << (idx & 31));
    }
    __syncthreads();

    #pragma unroll
    for (int i = 0; i < NPTS / 1024; i++) {
        int n = t + i * 1024;
        unsigned m = 0;
        #pragma unroll
        for (int k = 0; k < OCC_K; k++) {
            int nx = px[i] + c_noff[k][0];
            int ny = py[i] + c_noff[k][1];
            int nz = pz[i] + c_noff[k][2];
            if ((unsigned)nx < GRID_DIM && (unsigned)ny < GRID_DIM &&
                (unsigned)nz < GRID_DIM) {
                int idx = (nx << 12) | (ny << 6) | nz;
                m |= ((bm[idx >> 5] >> (idx & 31)) & 1u) << k;
            }
        }
        g_mask26[b * NPTS + n] = m;     // coalesced 4B store
    }
}

// Kernel 2: pure output stream. One CTA per (b,n), 256 threads.
// NO probes, NO shared memory, NO __syncthreads — warps fully independent.
// One converged broadcast mask load; threads 0..25 write occ; all 256
// threads stream the 4096-float prior tile as 4 fully contiguous warp-wide
// float4 stores each.
__global__ __launch_bounds__(256, 8)
void prior_occ_kernel(float* __restrict__ out) {
    const int bn = blockIdx.x;
    const int t  = threadIdx.x;

    const unsigned m26 = __ldcg(&g_mask26[bn]);   // broadcast: 1 req/warp
    if (t < OCC_K)
        out[OCC_BASE + (size_t)bn * OCC_K + t] = (m26 >> t) & 1u ? 1.0f : 0.0f;

    const unsigned m = m26 & 63u;
    const float r15 = 1.0f / 15.0f;
    float* out_p = out + (size_t)bn * PRIOR_VOX;

    // v = t*4 + q*1024; i = (t>>6) + 4q, j = (t>>2)&15, k0 = (t&3)*4.
    // y- and z-face mins are invariant across the 4 q iterations.
    const float gy = (float)((t >> 2) & 15) * r15;
    const int   k0 = (t & 3) << 2;
    const int   i0 = t >> 6;

    float ybase = 1.0f;
    if (!(m & 4u))  ybase = fminf(ybase, gy);
    if (!(m & 8u))  ybase = fminf(ybase, 1.0f - gy);

    float yz[4];
    #pragma unroll
    for (int kk = 0; kk < 4; kk++) {
        float gz = (float)(k0 + kk) * r15;
        float v = ybase;
        if (!(m & 16u)) v = fminf(v, gz);
        if (!(m & 32u)) v = fminf(v, 1.0f - gz);
        yz[kk] = v;
    }

    #pragma unroll
    for (int q = 0; q < 4; q++) {
        float gx = (float)(i0 + 4 * q) * r15;   // exact: matches linspace rounding
        float xv = 1.0f;
        if (!(m & 1u)) xv = fminf(xv, gx);
        if (!(m & 2u)) xv = fminf(xv, 1.0f - gx);
        float4 r;
        r.x = fminf(yz[0], xv);
        r.y = fminf(yz[1], xv);
        r.z = fminf(yz[2], xv);
        r.w = fminf(yz[3], xv);
        *reinterpret_cast<float4*>(out_p + (t << 2) + (q << 10)) = r;
    }
}

extern "C" void kernel_launch(void* const* d_in, const int* in_sizes, int n_in,
                              void* d_out, int out_size) {
    const int* coords = (const int*)d_in[0];
    float* out = (float*)d_out;

    mask_kernel<<<BATCH, 1024>>>(coords);
    prior_occ_kernel<<<NB, 256>>>(out);
}

// round 17
// speedup vs baseline: 1.1706x; 1.0870x over previous
#include <cuda_runtime.h>
#include <stdint.h>

// Problem constants (fixed shapes per setup_inputs)
#define BATCH 4
#define NPTS  2048
#define NB    (BATCH * NPTS)        // 8192 (b,n) pairs
#define GRID_DIM 64                 // coords in [0,64)
#define BITMAP_WORDS (GRID_DIM * GRID_DIM * GRID_DIM / 32)  // 8192 words = 32KB
#define PRIOR_VOX 4096              // 16^3
#define OCC_K 26
#define OCC_BASE ((size_t)NB * PRIOR_VOX)   // 33,554,432

#define SLICES_PER_BATCH 32
#define PTS_PER_SLICE (NPTS / SLICES_PER_BATCH)   // 64
#define MASK_GRID (BATCH * SLICES_PER_BATCH)      // 128 CTAs -> spread probes chip-wide

// Per-(b,n) 26-bit neighbor mask (32 KB, static __device__ per harness rules).
__device__ unsigned int g_mask26[NB];

// 26 neighbor offsets; first 6 are the face offsets (order matches reference).
__constant__ int8_t c_noff[26][3] = {
    {-1,0,0},{1,0,0},{0,-1,0},{0,1,0},{0,0,-1},{0,0,1},
    {-1,-1,0},{-1,1,0},{1,-1,0},{1,1,0},
    {-1,0,-1},{-1,0,1},{1,0,-1},{1,0,1},
    {0,-1,-1},{0,-1,1},{0,1,-1},{0,1,1},
    {-1,-1,-1},{-1,-1,1},{-1,1,-1},{-1,1,1},
    {1,-1,-1},{1,-1,1},{1,1,-1},{1,1,1}};

// Kernel 1: REPLICATED smem bitmap, 128 CTAs (32 per batch).
// Each CTA zeroes a private 32KB smem bitmap, builds it from ALL 2048 points
// of its batch (coords broadcast from L2; smem atomics, spread addresses),
// then probes only its 64-point slice (threads 0..63, 26 independent LDS
// each). Probe work is spread across ~128 SMs instead of 4 (the R16 mistake).
__global__ __launch_bounds__(256)
void mask_kernel(const int* __restrict__ coords) {
    __shared__ unsigned int bm[BITMAP_WORDS];   // 32 KB
    const int b     = blockIdx.x >> 5;          // batch
    const int slice = blockIdx.x & 31;
    const int t     = threadIdx.x;

    uint4* bm4 = reinterpret_cast<uint4*>(bm);
    const uint4 z4 = make_uint4(0u, 0u, 0u, 0u);
    #pragma unroll
    for (int i = 0; i < BITMAP_WORDS / 4 / 256; i++)   // 8 x STS.128
        bm4[t + i * 256] = z4;
    __syncthreads();

    const int* c = coords + b * NPTS * 3;
    #pragma unroll
    for (int i = 0; i < NPTS / 256; i++) {             // 8 smem atomics/thread
        int n = t + i * 256;
        int x = __ldg(&c[n * 3 + 0]);
        int y = __ldg(&c[n * 3 + 1]);
        int z = __ldg(&c[n * 3 + 2]);
        int idx = (x << 12) | (y << 6) | z;            // x*4096+y*64+z
        atomicOr(&bm[idx >> 5], 1u << (idx & 31));
    }
    __syncthreads();

    // Probe this CTA's 64-point slice: one point per thread (threads 0..63),
    // 26 independent LDS each (deep MLP, no cross-thread deps).
    if (t < PTS_PER_SLICE) {
        int n = slice * PTS_PER_SLICE + t;
        int x = c[n * 3 + 0];
        int y = c[n * 3 + 1];
        int z = c[n * 3 + 2];
        unsigned m = 0;
        #pragma unroll
        for (int k = 0; k < OCC_K; k++) {
            int nx = x + c_noff[k][0];
            int ny = y + c_noff[k][1];
            int nz = z + c_noff[k][2];
            if ((unsigned)nx < GRID_DIM && (unsigned)ny < GRID_DIM &&
                (unsigned)nz < GRID_DIM) {
                int idx = (nx << 12) | (ny << 6) | nz;
                m |= ((bm[idx >> 5] >> (idx & 31)) & 1u) << k;
            }
        }
        g_mask26[b * NPTS + n] = m;     // coalesced 4B store
    }
}

// Kernel 2 (PROVEN, 22.75us): pure output stream. One CTA per (b,n), 256
// threads. No probes, no shared memory, no __syncthreads — warps fully
// independent. One converged broadcast mask load; threads 0..25 write occ;
// all 256 threads stream the 4096-float prior tile as 4 fully contiguous
// warp-wide float4 stores each.
__global__ __launch_bounds__(256, 8)
void prior_occ_kernel(float* __restrict__ out) {
    const int bn = blockIdx.x;
    const int t  = threadIdx.x;

    const unsigned m26 = __ldcg(&g_mask26[bn]);   // broadcast: 1 req/warp
    if (t < OCC_K)
        out[OCC_BASE + (size_t)bn * OCC_K + t] = (m26 >> t) & 1u ? 1.0f : 0.0f;

    const unsigned m = m26 & 63u;
    const float r15 = 1.0f / 15.0f;
    float* out_p = out + (size_t)bn * PRIOR_VOX;

    // v = t*4 + q*1024; i = (t>>6) + 4q, j = (t>>2)&15, k0 = (t&3)*4.
    // y- and z-face mins are invariant across the 4 q iterations.
    const float gy = (float)((t >> 2) & 15) * r15;
    const int   k0 = (t & 3) << 2;
    const int   i0 = t >> 6;

    float ybase = 1.0f;
    if (!(m & 4u))  ybase = fminf(ybase, gy);
    if (!(m & 8u))  ybase = fminf(ybase, 1.0f - gy);

    float yz[4];
    #pragma unroll
    for (int kk = 0; kk < 4; kk++) {
        float gz = (float)(k0 + kk) * r15;
        float v = ybase;
        if (!(m & 16u)) v = fminf(v, gz);
        if (!(m & 32u)) v = fminf(v, 1.0f - gz);
        yz[kk] = v;
    }

    #pragma unroll
    for (int q = 0; q < 4; q++) {
        float gx = (float)(i0 + 4 * q) * r15;   // exact: matches linspace rounding
        float xv = 1.0f;
        if (!(m & 1u)) xv = fminf(xv, gx);
        if (!(m & 2u)) xv = fminf(xv, 1.0f - gx);
        float4 r;
        r.x = fminf(yz[0], xv);
        r.y = fminf(yz[1], xv);
        r.z = fminf(yz[2], xv);
        r.w = fminf(yz[3], xv);
        *reinterpret_cast<float4*>(out_p + (t << 2) + (q << 10)) = r;
    }
}

extern "C" void kernel_launch(void* const* d_in, const int* in_sizes, int n_in,
                              void* d_out, int out_size) {
    const int* coords = (const int*)d_in[0];
    float* out = (float*)d_out;

    mask_kernel<<<MASK_GRID, 256>>>(coords);
    prior_occ_kernel<<<NB, 256>>>(out);
}